// round 12
// baseline (speedup 1.0000x reference)
#include <cuda_runtime.h>
#include <cuda_fp16.h>
#include <stdint.h>

// Problem constants (fixed shapes for this problem instance)
#define NN 50000       // nodes
#define EE 800000      // edges
#define MM 8           // B*T
#define CC 32          // in channels
#define OO 32          // out channels
#define FF 256         // MM*CC features per node
#define BN_EPS 1e-5f
#define SCAN_NBLK 13   // ceil(NN / 4096)

// ---------------- scratch (device globals; no allocation allowed) -------------
// Launch order relies on these being zero at entry: first call uses CUDA static
// zero-init; k_cleanup (last launch) restores zeroed state for every replay.
__device__ float g_deg[NN];
__device__ float g_dinv[NN];
__device__ int   g_cnt[NN];          // histogram by dst, reused as fill cursor
__device__ int   g_rowptr[NN + 1];
__device__ __align__(16) uint2 g_edge[EE];              // (src, half2(w,w))
__device__ __align__(16) __half g_xh[(size_t)NN * FF];  // x, node-major fp16
__device__ __align__(16) __half g_t1h[(size_t)NN * FF]; // L x (fp16)
__device__ __align__(16) __half g_t2h[(size_t)NN * FF]; // L(Lx) raw (fp16)
__device__ __align__(16) float g_outpre[(size_t)NN * FF]; // pre-BN [r=n*8+m][32]
__device__ float g_bnsum[MM * OO];
__device__ float g_bnsq[MM * OO];
__device__ float g_scale[MM * OO];
__device__ float g_shift[MM * OO];
__device__ int   g_scan_val[SCAN_NBLK];
__device__ int   g_scan_flag[SCAN_NBLK];

// ---------------- mma helpers ---------------------------------------------------
__device__ __forceinline__ void ldm_x4(uint32_t& r0, uint32_t& r1,
                                       uint32_t& r2, uint32_t& r3, uint32_t a) {
    asm volatile("ldmatrix.sync.aligned.m8n8.x4.shared.b16 {%0,%1,%2,%3}, [%4];"
                 : "=r"(r0), "=r"(r1), "=r"(r2), "=r"(r3) : "r"(a));
}
__device__ __forceinline__ void mma16816(float* d, uint32_t a0, uint32_t a1,
                                         uint32_t a2, uint32_t a3,
                                         uint32_t b0, uint32_t b1) {
    asm volatile(
        "mma.sync.aligned.m16n8k16.row.col.f32.f16.f16.f32 "
        "{%0,%1,%2,%3}, {%4,%5,%6,%7}, {%8,%9}, {%0,%1,%2,%3};"
        : "+f"(d[0]), "+f"(d[1]), "+f"(d[2]), "+f"(d[3])
        : "r"(a0), "r"(a1), "r"(a2), "r"(a3), "r"(b0), "r"(b1));
}

// ---------------- 1: degree/count atomics + x->fp16 conversion (fused) ---------
__global__ void k_degcnt_xconv(const float* __restrict__ x,
                               const int* __restrict__ ei,
                               const float* __restrict__ ew) {
    int t = blockIdx.x * blockDim.x + threadIdx.x;
    if (t < EE) {
        int s = ei[t];
        int d = ei[EE + t];
        atomicAdd(&g_deg[s], ew[t]);
        atomicAdd(&g_cnt[d], 1);
    }
    if (t < NN * MM * 16) {
        int c2 = t & 15;
        int m = (t >> 4) & 7;
        int n = t >> 7;
        float2 v = *(const float2*)&x[((size_t)m * NN + n) * CC + c2 * 2];
        *(__half2*)&g_xh[(size_t)n * FF + m * CC + c2 * 2] =
            __floats2half2_rn(v.x, v.y);
    }
}

// ---------------- 2: scan(cnt)->rowptr  +  dinv (fused) ------------------------
__global__ void k_scan_dinv() {
    __shared__ int s_wsum[8];
    __shared__ int s_prev;
    int tid = threadIdx.x, b = blockIdx.x;
    int lane = tid & 31, w = tid >> 5;

    for (int i = b * 4096 + tid; i < (b + 1) * 4096 && i < NN; i += 256) {
        float dg = g_deg[i];
        g_dinv[i] = (dg > 0.f) ? rsqrtf(dg) : 0.f;
    }

    int base = b * 4096 + tid * 16;
    int v[16];
    int run = 0;
    #pragma unroll
    for (int j = 0; j < 16; j++) {
        int i = base + j;
        int c = 0;
        if (i < NN) { c = g_cnt[i]; g_cnt[i] = 0; }
        run += c;
        v[j] = run;   // inclusive within thread
    }
    int sc = run;
    #pragma unroll
    for (int off = 1; off < 32; off <<= 1) {
        int t2 = __shfl_up_sync(0xffffffffu, sc, off);
        if (lane >= off) sc += t2;
    }
    if (lane == 31) s_wsum[w] = sc;
    __syncthreads();
    if (w == 0) {
        int xv = (lane < 8) ? s_wsum[lane] : 0;
        #pragma unroll
        for (int off = 1; off < 8; off <<= 1) {
            int t2 = __shfl_up_sync(0xffffffffu, xv, off);
            if (lane >= off) xv += t2;
        }
        if (lane < 8) s_wsum[lane] = xv;
    }
    __syncthreads();
    int thread_excl = sc - run + (w ? s_wsum[w - 1] : 0);
    int block_total = s_wsum[7];
    if (tid == 0) {
        int prev = 0;
        if (b > 0) {
            while (((volatile int*)g_scan_flag)[b - 1] == 0) { }
            __threadfence();
            prev = g_scan_val[b - 1];
        }
        g_scan_val[b] = prev + block_total;
        __threadfence();
        ((volatile int*)g_scan_flag)[b] = 1;
        s_prev = prev;
    }
    __syncthreads();
    int off0 = s_prev + thread_excl;
    #pragma unroll
    for (int j = 0; j < 16; j++) {
        int i = base + j;
        if (i < NN) g_rowptr[i + 1] = off0 + v[j];
    }
    if (b == 0 && tid == 0) g_rowptr[0] = 0;
}

// ---------------- 3: CSR fill, packed (src, half2(w,w)) ------------------------
__global__ void k_fill(const int* __restrict__ ei,
                       const float* __restrict__ ew) {
    int e = blockIdx.x * blockDim.x + threadIdx.x;
    if (e >= EE) return;
    int s = ei[e];
    int d = ei[EE + e];
    float nv = -g_dinv[s] * ew[e] * g_dinv[d];
    unsigned short h = __half_as_ushort(__float2half_rn(nv));
    unsigned hw = (unsigned)h | ((unsigned)h << 16);   // half2(w, w)
    int idx = g_rowptr[d] + atomicAdd(&g_cnt[d], 1);
    g_edge[idx] = make_uint2((unsigned)s, hw);
}

// ---------------- 4/5: SpMM (fp16 gather, HFMA2 split accumulation) ------------
// One warp per dst row; lane owns 8 halves (16B). Per edge per warp:
// 1 LDG.128 gather + 0.5 LDG.128 (paired edges) + 4 HFMA2 + addr.
// Even/odd edges go to separate half2 accumulators (halves rounding walk);
// final sum in fp32.
__device__ __forceinline__ void hacc(__half2* acc, uint4 v, unsigned w) {
    __half2 w2 = *(__half2*)&w;
    const __half2* h = (const __half2*)&v;
    acc[0] = __hfma2(h[0], w2, acc[0]);
    acc[1] = __hfma2(h[1], w2, acc[1]);
    acc[2] = __hfma2(h[2], w2, acc[2]);
    acc[3] = __hfma2(h[3], w2, acc[3]);
}

template <int MODE>
__global__ void __launch_bounds__(256) k_spmm_h() {
    int row = (blockIdx.x * blockDim.x + threadIdx.x) >> 5;
    int lane = threadIdx.x & 31;
    if (row >= NN) return;
    int e = g_rowptr[row];
    int end = g_rowptr[row + 1];

    const char* __restrict__ vin =
        (MODE == 0) ? (const char*)g_xh : (const char*)g_t1h;
    uint4* __restrict__ vout =
        (MODE == 0) ? (uint4*)g_t1h : (uint4*)g_t2h;

    __half2 zero = __floats2half2_rn(0.f, 0.f);
    __half2 accA[4] = {zero, zero, zero, zero};
    __half2 accB[4] = {zero, zero, zero, zero};
    unsigned lb = (unsigned)lane << 4;

    // peel to 16B-aligned edge pair
    if ((e & 1) && e < end) {
        uint2 E = g_edge[e];
        uint4 V = *(const uint4*)(vin + ((E.x << 9) + lb));
        hacc(accA, V, E.y);
        e++;
    }
    #pragma unroll 1
    while (e + 4 <= end) {
        uint4 P0 = *(const uint4*)&g_edge[e];       // edges e, e+1
        uint4 P1 = *(const uint4*)&g_edge[e + 2];   // edges e+2, e+3
        uint4 V0 = *(const uint4*)(vin + ((P0.x << 9) + lb));
        uint4 V1 = *(const uint4*)(vin + ((P0.z << 9) + lb));
        uint4 V2 = *(const uint4*)(vin + ((P1.x << 9) + lb));
        uint4 V3 = *(const uint4*)(vin + ((P1.z << 9) + lb));
        hacc(accA, V0, P0.y);
        hacc(accB, V1, P0.w);
        hacc(accA, V2, P1.y);
        hacc(accB, V3, P1.w);
        e += 4;
    }
    if (e + 2 <= end) {
        uint4 P0 = *(const uint4*)&g_edge[e];
        uint4 V0 = *(const uint4*)(vin + ((P0.x << 9) + lb));
        uint4 V1 = *(const uint4*)(vin + ((P0.z << 9) + lb));
        hacc(accA, V0, P0.y);
        hacc(accB, V1, P0.w);
        e += 2;
    }
    if (e < end) {
        uint2 E = g_edge[e];
        uint4 V = *(const uint4*)(vin + ((E.x << 9) + lb));
        hacc(accA, V, E.y);
    }

    // combine split accumulators in fp32, round once to fp16
    uint4 o;
    #pragma unroll
    for (int i = 0; i < 4; i++) {
        float2 fa = __half22float2(accA[i]);
        float2 fb = __half22float2(accB[i]);
        ((__half2*)&o)[i] = __floats2half2_rn(fa.x + fb.x, fa.y + fb.y);
    }
    vout[(size_t)row * 32 + lane] = o;
}

// ---------------- 6: combine via tensor cores + fused BN partial sums ----------
// out[r,:] = x[r]@(W0-W2) + t1[r]@W1 + t2[r]@(2*W2) + bias,  r = n*8+m.
#define SAS 104   // smem row stride in halves (96 data + 8 pad)
__global__ void __launch_bounds__(256) k_combine_mma(const float* __restrict__ W,
                                                     const float* __restrict__ bias) {
    __shared__ __align__(16) __half sA[128 * SAS];
    __shared__ __align__(16) __half sW[32 * SAS];
    __shared__ float sB[OO];
    __shared__ float sSum[MM][OO], sSq[MM][OO];
    int tid = threadIdx.x;

    // weight prep: Wt[o][k]: k<32 -> W0-W2, k<64 -> W1, else 2*W2
    for (int i = tid; i < 32 * 96; i += 256) {
        int o = i / 96, k = i % 96;
        float v;
        if (k < 32)      v = W[k * 32 + o] - W[2048 + k * 32 + o];
        else if (k < 64) v = W[1024 + (k - 32) * 32 + o];
        else             v = 2.f * W[2048 + (k - 64) * 32 + o];
        sW[o * SAS + k] = __float2half_rn(v);
    }
    if (tid < OO) sB[tid] = bias[tid];
    sSum[tid >> 5][tid & 31] = 0.f;
    sSq[tid >> 5][tid & 31] = 0.f;

    // stage A rows: 128 rows x (x|t1|t2) = 128 x 96 halves
    int rbase = blockIdx.x * 128;
    const uint4* gx = (const uint4*)g_xh + (size_t)rbase * 4;
    const uint4* g1 = (const uint4*)g_t1h + (size_t)rbase * 4;
    const uint4* g2 = (const uint4*)g_t2h + (size_t)rbase * 4;
    for (int i = tid; i < 512; i += 256) {   // 128 rows x 4 16B-chunks
        int rl = i >> 2, q = i & 3;
        *(uint4*)&sA[rl * SAS + q * 8]      = gx[i];
        *(uint4*)&sA[rl * SAS + 32 + q * 8] = g1[i];
        *(uint4*)&sA[rl * SAS + 64 + q * 8] = g2[i];
    }
    __syncthreads();

    int w = tid >> 5, l = tid & 31;
    int colb = (l & 3) * 2;

    float d[4][4];
    #pragma unroll
    for (int t = 0; t < 4; t++) {
        float b0 = sB[t * 8 + colb], b1 = sB[t * 8 + colb + 1];
        d[t][0] = b0; d[t][1] = b1; d[t][2] = b0; d[t][3] = b1;
    }

    int rowi = l & 7;
    int quad = l >> 3;
    int r_loc = w * 16 + rowi + (quad & 1) * 8;
    int cq = (quad >> 1) * 8;
    uint32_t abase = (uint32_t)__cvta_generic_to_shared(&sA[r_loc * SAS + cq]);

    #pragma unroll
    for (int ks = 0; ks < 6; ks++) {
        int c0 = ks * 16;
        uint32_t a0, a1, a2, a3;
        ldm_x4(a0, a1, a2, a3, abase + c0 * 2);
        #pragma unroll
        for (int t = 0; t < 4; t++) {
            int n = t * 8 + (l >> 2);
            uint32_t b0 = *(const uint32_t*)&sW[n * SAS + c0 + colb];
            uint32_t b1 = *(const uint32_t*)&sW[n * SAS + c0 + 8 + colb];
            mma16816(d[t], a0, a1, a2, a3, b0, b1);
        }
    }

    // store D + accumulate BN partials. rows r0, r0+8 share m = r0&7.
    int r0 = rbase + w * 16 + (l >> 2);
    int mloc = r0 & 7;
    #pragma unroll
    for (int t = 0; t < 4; t++) {
        int c = t * 8 + colb;
        *(float2*)&g_outpre[(size_t)r0 * 32 + c] = make_float2(d[t][0], d[t][1]);
        *(float2*)&g_outpre[(size_t)(r0 + 8) * 32 + c] = make_float2(d[t][2], d[t][3]);
        // within a warp each (mloc, c) is touched by exactly one lane
        atomicAdd(&sSum[mloc][c],     d[t][0] + d[t][2]);
        atomicAdd(&sSum[mloc][c + 1], d[t][1] + d[t][3]);
        atomicAdd(&sSq[mloc][c],     d[t][0] * d[t][0] + d[t][2] * d[t][2]);
        atomicAdd(&sSq[mloc][c + 1], d[t][1] * d[t][1] + d[t][3] * d[t][3]);
    }
    __syncthreads();
    atomicAdd(&g_bnsum[tid], sSum[tid >> 5][tid & 31]);
    atomicAdd(&g_bnsq[tid], sSq[tid >> 5][tid & 31]);
}

// ---------------- 7: finalize BN stats -> scale/shift --------------------------
__global__ void k_finalize(const float* __restrict__ gamma,
                           const float* __restrict__ beta) {
    int i = threadIdx.x;  // 0..255 = (m, o)
    if (i >= MM * OO) return;
    int o = i & 31;
    float mean = g_bnsum[i] * (1.f / NN);
    float var = g_bnsq[i] * (1.f / NN) - mean * mean;
    float sc = gamma[o] * rsqrtf(var + BN_EPS);
    g_scale[i] = sc;
    g_shift[i] = beta[o] - mean * sc;
}

// ---------------- 8: normalize + relu + transpose via shared tile ---------------
#define TN 32
#define SHF4 65   // padded row stride in float4 (64 data + 1 pad)
__global__ void k_output(float* __restrict__ out) {
    __shared__ __align__(16) float4 sh[TN * SHF4];
    __shared__ float ssc[MM * OO], ssh[MM * OO];
    int tid = threadIdx.x;
    int nbase = blockIdx.x * TN;
    int nmax = NN - nbase; if (nmax > TN) nmax = TN;

    ssc[tid] = g_scale[tid];
    ssh[tid] = g_shift[tid];

    const float4* src = (const float4*)&g_outpre[(size_t)nbase * FF];
    for (int i = tid; i < nmax * 64; i += 256) {
        int nl = i >> 6, j = i & 63;
        sh[nl * SHF4 + j] = src[i];
    }
    __syncthreads();

    for (int i = tid; i < MM * TN * 8; i += 256) {
        int m = i >> 8;
        int nl = (i >> 3) & 31;
        int o4 = i & 7;
        if (nl >= nmax) continue;
        float4 v = sh[nl * SHF4 + m * 8 + o4];
        int si = m * OO + o4 * 4;
        float4 r;
        r.x = fmaxf(0.f, v.x * ssc[si + 0] + ssh[si + 0]);
        r.y = fmaxf(0.f, v.y * ssc[si + 1] + ssh[si + 1]);
        r.z = fmaxf(0.f, v.z * ssc[si + 2] + ssh[si + 2]);
        r.w = fmaxf(0.f, v.w * ssc[si + 3] + ssh[si + 3]);
        ((float4*)out)[((size_t)m * NN + nbase + nl) * 8 + o4] = r;
    }
}

// ---------------- 9: cleanup -> restore zeroed state for next replay -----------
__global__ void k_cleanup() {
    int i = blockIdx.x * blockDim.x + threadIdx.x;
    if (i < NN) { g_deg[i] = 0.f; g_cnt[i] = 0; }
    if (i < MM * OO) { g_bnsum[i] = 0.f; g_bnsq[i] = 0.f; }
    if (i < SCAN_NBLK) { g_scan_flag[i] = 0; g_scan_val[i] = 0; }
}

// ------------------------------------------------------------------------------
extern "C" void kernel_launch(void* const* d_in, const int* in_sizes, int n_in,
                              void* d_out, int out_size) {
    const float* x      = (const float*)d_in[0];
    const int*   ei     = (const int*)d_in[1];
    const float* ew     = (const float*)d_in[2];
    const float* W      = (const float*)d_in[3];
    const float* bias   = (const float*)d_in[4];
    const float* gamma  = (const float*)d_in[5];
    const float* beta   = (const float*)d_in[6];
    float* out          = (float*)d_out;

    k_degcnt_xconv<<<(NN * MM * 16 + 255) / 256, 256>>>(x, ei, ew);  // 1
    k_scan_dinv<<<SCAN_NBLK, 256>>>();                               // 2
    k_fill<<<(EE + 255) / 256, 256>>>(ei, ew);                       // 3
    k_spmm_h<0><<<(NN * 32 + 255) / 256, 256>>>();                   // 4 <- profiled
    k_spmm_h<1><<<(NN * 32 + 255) / 256, 256>>>();                   // 5
    k_combine_mma<<<(NN * MM) / 128, 256>>>(W, bias);                // 6
    k_finalize<<<1, 256>>>(gamma, beta);                             // 7
    k_output<<<(NN + TN - 1) / TN, 256>>>(out);                      // 8
    k_cleanup<<<(NN + 255) / 256, 256>>>();                          // 9
}

// round 13
// speedup vs baseline: 1.0653x; 1.0653x over previous
#include <cuda_runtime.h>
#include <cuda_fp16.h>
#include <stdint.h>

// Problem constants (fixed shapes for this problem instance)
#define NN 50000       // nodes
#define EE 800000      // edges
#define MM 8           // B*T
#define CC 32          // in channels
#define OO 32          // out channels
#define FF 256         // MM*CC features per node
#define BN_EPS 1e-5f
#define SCAN_NBLK 13   // ceil(NN / 4096)

// ---------------- scratch (device globals; no allocation allowed) -------------
// Launch order relies on these being zero at entry: first call uses CUDA static
// zero-init; k_cleanup (last launch) restores zeroed state for every replay.
__device__ float g_deg[NN];
__device__ float g_dinv[NN];
__device__ int   g_cnt[NN];          // histogram by dst, reused as fill cursor
__device__ int   g_rowptr[NN + 1];
__device__ __align__(16) uint2 g_edge[EE];              // (src, half2(w,w))
__device__ __align__(16) __half g_xh[(size_t)NN * FF];  // x, node-major fp16
__device__ __align__(16) __half g_t1h[(size_t)NN * FF]; // L x (fp16)
__device__ __align__(16) __half g_t2h[(size_t)NN * FF]; // L(Lx) raw (fp16)
__device__ __align__(16) float g_outpre[(size_t)NN * FF]; // pre-BN [r=n*8+m][32]
__device__ float g_bnsum[MM * OO];
__device__ float g_bnsq[MM * OO];
__device__ float g_scale[MM * OO];
__device__ float g_shift[MM * OO];
__device__ int   g_scan_val[SCAN_NBLK];
__device__ int   g_scan_flag[SCAN_NBLK];

// ---------------- mma helpers ---------------------------------------------------
__device__ __forceinline__ void ldm_x4(uint32_t& r0, uint32_t& r1,
                                       uint32_t& r2, uint32_t& r3, uint32_t a) {
    asm volatile("ldmatrix.sync.aligned.m8n8.x4.shared.b16 {%0,%1,%2,%3}, [%4];"
                 : "=r"(r0), "=r"(r1), "=r"(r2), "=r"(r3) : "r"(a));
}
__device__ __forceinline__ void mma16816(float* d, uint32_t a0, uint32_t a1,
                                         uint32_t a2, uint32_t a3,
                                         uint32_t b0, uint32_t b1) {
    asm volatile(
        "mma.sync.aligned.m16n8k16.row.col.f32.f16.f16.f32 "
        "{%0,%1,%2,%3}, {%4,%5,%6,%7}, {%8,%9}, {%0,%1,%2,%3};"
        : "+f"(d[0]), "+f"(d[1]), "+f"(d[2]), "+f"(d[3])
        : "r"(a0), "r"(a1), "r"(a2), "r"(a3), "r"(b0), "r"(b1));
}

// ---------------- 1: degree/count atomics + x->fp16 conversion (fused) ---------
__global__ void k_degcnt_xconv(const float* __restrict__ x,
                               const int* __restrict__ ei,
                               const float* __restrict__ ew) {
    int t = blockIdx.x * blockDim.x + threadIdx.x;
    if (t < EE) {
        int s = ei[t];
        int d = ei[EE + t];
        atomicAdd(&g_deg[s], ew[t]);
        atomicAdd(&g_cnt[d], 1);
    }
    if (t < NN * MM * 16) {
        int c2 = t & 15;
        int m = (t >> 4) & 7;
        int n = t >> 7;
        float2 v = *(const float2*)&x[((size_t)m * NN + n) * CC + c2 * 2];
        *(__half2*)&g_xh[(size_t)n * FF + m * CC + c2 * 2] =
            __floats2half2_rn(v.x, v.y);
    }
}

// ---------------- 2: scan(cnt)->rowptr  +  dinv (fused) ------------------------
__global__ void k_scan_dinv() {
    __shared__ int s_wsum[8];
    __shared__ int s_prev;
    int tid = threadIdx.x, b = blockIdx.x;
    int lane = tid & 31, w = tid >> 5;

    for (int i = b * 4096 + tid; i < (b + 1) * 4096 && i < NN; i += 256) {
        float dg = g_deg[i];
        g_dinv[i] = (dg > 0.f) ? rsqrtf(dg) : 0.f;
    }

    int base = b * 4096 + tid * 16;
    int v[16];
    int run = 0;
    #pragma unroll
    for (int j = 0; j < 16; j++) {
        int i = base + j;
        int c = 0;
        if (i < NN) { c = g_cnt[i]; g_cnt[i] = 0; }
        run += c;
        v[j] = run;   // inclusive within thread
    }
    int sc = run;
    #pragma unroll
    for (int off = 1; off < 32; off <<= 1) {
        int t2 = __shfl_up_sync(0xffffffffu, sc, off);
        if (lane >= off) sc += t2;
    }
    if (lane == 31) s_wsum[w] = sc;
    __syncthreads();
    if (w == 0) {
        int xv = (lane < 8) ? s_wsum[lane] : 0;
        #pragma unroll
        for (int off = 1; off < 8; off <<= 1) {
            int t2 = __shfl_up_sync(0xffffffffu, xv, off);
            if (lane >= off) xv += t2;
        }
        if (lane < 8) s_wsum[lane] = xv;
    }
    __syncthreads();
    int thread_excl = sc - run + (w ? s_wsum[w - 1] : 0);
    int block_total = s_wsum[7];
    if (tid == 0) {
        int prev = 0;
        if (b > 0) {
            while (((volatile int*)g_scan_flag)[b - 1] == 0) { }
            __threadfence();
            prev = g_scan_val[b - 1];
        }
        g_scan_val[b] = prev + block_total;
        __threadfence();
        ((volatile int*)g_scan_flag)[b] = 1;
        s_prev = prev;
    }
    __syncthreads();
    int off0 = s_prev + thread_excl;
    #pragma unroll
    for (int j = 0; j < 16; j++) {
        int i = base + j;
        if (i < NN) g_rowptr[i + 1] = off0 + v[j];
    }
    if (b == 0 && tid == 0) g_rowptr[0] = 0;
}

// ---------------- 3: CSR fill, packed (src, half2(w,w)) ------------------------
__global__ void k_fill(const int* __restrict__ ei,
                       const float* __restrict__ ew) {
    int e = blockIdx.x * blockDim.x + threadIdx.x;
    if (e >= EE) return;
    int s = ei[e];
    int d = ei[EE + e];
    float nv = -g_dinv[s] * ew[e] * g_dinv[d];
    unsigned short h = __half_as_ushort(__float2half_rn(nv));
    unsigned hw = (unsigned)h | ((unsigned)h << 16);   // half2(w, w)
    int idx = g_rowptr[d] + atomicAdd(&g_cnt[d], 1);
    g_edge[idx] = make_uint2((unsigned)s, hw);
}

// ---------------- 4/5: SpMM — 2 rows/warp, HFMA2 split accumulation ------------
// Each warp owns rows 2g and 2g+1 (independent edge streams -> 2x MLP).
// Lane owns 8 halves (16B) of each row. Per row, even/odd edges accumulate
// into separate half2 chains; the two chains are summed in fp32 at the end.
__device__ __forceinline__ void hacc(__half2* acc, uint4 v, unsigned w) {
    __half2 w2 = *(__half2*)&w;
    const __half2* h = (const __half2*)&v;
    acc[0] = __hfma2(h[0], w2, acc[0]);
    acc[1] = __hfma2(h[1], w2, acc[1]);
    acc[2] = __hfma2(h[2], w2, acc[2]);
    acc[3] = __hfma2(h[3], w2, acc[3]);
}

template <int MODE>
__global__ void __launch_bounds__(256) k_spmm_h() {
    int gw = (blockIdx.x * blockDim.x + threadIdx.x) >> 5;
    int lane = threadIdx.x & 31;
    if (gw >= NN / 2) return;
    int rowA = gw * 2;
    int rowB = rowA + 1;
    int eA = g_rowptr[rowA], endA = g_rowptr[rowA + 1];
    int eB = g_rowptr[rowB], endB = g_rowptr[rowB + 1];

    const char* __restrict__ vin =
        (MODE == 0) ? (const char*)g_xh : (const char*)g_t1h;
    uint4* __restrict__ vout =
        (MODE == 0) ? (uint4*)g_t1h : (uint4*)g_t2h;

    __half2 zero = __floats2half2_rn(0.f, 0.f);
    __half2 aA0[4] = {zero, zero, zero, zero};
    __half2 aA1[4] = {zero, zero, zero, zero};
    __half2 aB0[4] = {zero, zero, zero, zero};
    __half2 aB1[4] = {zero, zero, zero, zero};
    unsigned lb = (unsigned)lane << 4;

    // co-iterate both rows: 4 edge loads + 4 gathers in flight
    #pragma unroll 1
    while (eA + 2 <= endA && eB + 2 <= endB) {
        uint2 EA0 = g_edge[eA], EA1 = g_edge[eA + 1];
        uint2 EB0 = g_edge[eB], EB1 = g_edge[eB + 1];
        uint4 VA0 = *(const uint4*)(vin + ((EA0.x << 9) + lb));
        uint4 VA1 = *(const uint4*)(vin + ((EA1.x << 9) + lb));
        uint4 VB0 = *(const uint4*)(vin + ((EB0.x << 9) + lb));
        uint4 VB1 = *(const uint4*)(vin + ((EB1.x << 9) + lb));
        hacc(aA0, VA0, EA0.y);
        hacc(aA1, VA1, EA1.y);
        hacc(aB0, VB0, EB0.y);
        hacc(aB1, VB1, EB1.y);
        eA += 2;
        eB += 2;
    }
    // drain row A (unroll 2)
    #pragma unroll 1
    while (eA + 2 <= endA) {
        uint2 E0 = g_edge[eA], E1 = g_edge[eA + 1];
        uint4 V0 = *(const uint4*)(vin + ((E0.x << 9) + lb));
        uint4 V1 = *(const uint4*)(vin + ((E1.x << 9) + lb));
        hacc(aA0, V0, E0.y);
        hacc(aA1, V1, E1.y);
        eA += 2;
    }
    if (eA < endA) {
        uint2 E0 = g_edge[eA];
        uint4 V0 = *(const uint4*)(vin + ((E0.x << 9) + lb));
        hacc(aA0, V0, E0.y);
    }
    // drain row B (unroll 2)
    #pragma unroll 1
    while (eB + 2 <= endB) {
        uint2 E0 = g_edge[eB], E1 = g_edge[eB + 1];
        uint4 V0 = *(const uint4*)(vin + ((E0.x << 9) + lb));
        uint4 V1 = *(const uint4*)(vin + ((E1.x << 9) + lb));
        hacc(aB0, V0, E0.y);
        hacc(aB1, V1, E1.y);
        eB += 2;
    }
    if (eB < endB) {
        uint2 E0 = g_edge[eB];
        uint4 V0 = *(const uint4*)(vin + ((E0.x << 9) + lb));
        hacc(aB0, V0, E0.y);
    }

    // combine split chains in fp32, round once to fp16, store both rows
    uint4 oA, oB;
    #pragma unroll
    for (int i = 0; i < 4; i++) {
        float2 fa = __half22float2(aA0[i]);
        float2 fb = __half22float2(aA1[i]);
        ((__half2*)&oA)[i] = __floats2half2_rn(fa.x + fb.x, fa.y + fb.y);
        float2 ga = __half22float2(aB0[i]);
        float2 gb = __half22float2(aB1[i]);
        ((__half2*)&oB)[i] = __floats2half2_rn(ga.x + gb.x, ga.y + gb.y);
    }
    vout[(size_t)rowA * 32 + lane] = oA;
    vout[(size_t)rowB * 32 + lane] = oB;
}

// ---------------- 6: combine via tensor cores (mma.sync m16n8k16) --------------
// out[r,:] = x[r]@(W0-W2) + t1[r]@W1 + t2[r]@(2*W2) + bias,  r = n*8+m.
#define SAS 104   // smem row stride in halves (96 data + 8 pad)
__global__ void __launch_bounds__(256) k_combine_mma(const float* __restrict__ W,
                                                     const float* __restrict__ bias) {
    __shared__ __align__(16) __half sA[128 * SAS];
    __shared__ __align__(16) __half sW[32 * SAS];
    __shared__ float sB[OO];
    int tid = threadIdx.x;

    // weight prep: Wt[o][k]: k<32 -> W0-W2, k<64 -> W1, else 2*W2
    for (int i = tid; i < 32 * 96; i += 256) {
        int o = i / 96, k = i % 96;
        float v;
        if (k < 32)      v = W[k * 32 + o] - W[2048 + k * 32 + o];
        else if (k < 64) v = W[1024 + (k - 32) * 32 + o];
        else             v = 2.f * W[2048 + (k - 64) * 32 + o];
        sW[o * SAS + k] = __float2half_rn(v);
    }
    if (tid < OO) sB[tid] = bias[tid];

    // stage A rows: 128 rows x (x|t1|t2) = 128 x 96 halves
    int rbase = blockIdx.x * 128;
    const uint4* gx = (const uint4*)g_xh + (size_t)rbase * 4;
    const uint4* g1 = (const uint4*)g_t1h + (size_t)rbase * 4;
    const uint4* g2 = (const uint4*)g_t2h + (size_t)rbase * 4;
    for (int i = tid; i < 512; i += 256) {   // 128 rows x 4 16B-chunks
        int rl = i >> 2, q = i & 3;
        *(uint4*)&sA[rl * SAS + q * 8]      = gx[i];
        *(uint4*)&sA[rl * SAS + 32 + q * 8] = g1[i];
        *(uint4*)&sA[rl * SAS + 64 + q * 8] = g2[i];
    }
    __syncthreads();

    int w = tid >> 5, l = tid & 31;
    int colb = (l & 3) * 2;

    float d[4][4];
    #pragma unroll
    for (int t = 0; t < 4; t++) {
        float b0 = sB[t * 8 + colb], b1 = sB[t * 8 + colb + 1];
        d[t][0] = b0; d[t][1] = b1; d[t][2] = b0; d[t][3] = b1;
    }

    int rowi = l & 7;
    int quad = l >> 3;
    int r_loc = w * 16 + rowi + (quad & 1) * 8;
    int cq = (quad >> 1) * 8;
    uint32_t abase = (uint32_t)__cvta_generic_to_shared(&sA[r_loc * SAS + cq]);

    #pragma unroll
    for (int ks = 0; ks < 6; ks++) {
        int c0 = ks * 16;
        uint32_t a0, a1, a2, a3;
        ldm_x4(a0, a1, a2, a3, abase + c0 * 2);
        #pragma unroll
        for (int t = 0; t < 4; t++) {
            int n = t * 8 + (l >> 2);
            uint32_t b0 = *(const uint32_t*)&sW[n * SAS + c0 + colb];
            uint32_t b1 = *(const uint32_t*)&sW[n * SAS + c0 + 8 + colb];
            mma16816(d[t], a0, a1, a2, a3, b0, b1);
        }
    }

    // store D: rows r0 (l>>2) and r0+8; cols t*8 + colb (+1)
    int r0 = rbase + w * 16 + (l >> 2);
    #pragma unroll
    for (int t = 0; t < 4; t++) {
        int c = t * 8 + colb;
        *(float2*)&g_outpre[(size_t)r0 * 32 + c] = make_float2(d[t][0], d[t][1]);
        *(float2*)&g_outpre[(size_t)(r0 + 8) * 32 + c] = make_float2(d[t][2], d[t][3]);
    }
}

// ---------------- 7: BN statistics (streaming, coalesced) ----------------------
__global__ void k_stats() {
    int tid = threadIdx.x;
    int nbase = blockIdx.x * 256;
    int rows = NN - nbase; if (rows > 256) rows = 256;
    float s0 = 0.f, sq0 = 0.f, s1 = 0.f, sq1 = 0.f;
    const float* p = &g_outpre[(size_t)nbase * FF + tid];
    int r = 0;
    #pragma unroll 4
    for (; r + 2 <= rows; r += 2) {
        float v0 = p[(size_t)r * FF];
        float v1 = p[(size_t)(r + 1) * FF];
        s0 += v0; sq0 += v0 * v0;
        s1 += v1; sq1 += v1 * v1;
    }
    if (r < rows) {
        float v0 = p[(size_t)r * FF];
        s0 += v0; sq0 += v0 * v0;
    }
    atomicAdd(&g_bnsum[tid], s0 + s1);
    atomicAdd(&g_bnsq[tid], sq0 + sq1);
}

// ---------------- 8: finalize BN stats -> scale/shift --------------------------
__global__ void k_finalize(const float* __restrict__ gamma,
                           const float* __restrict__ beta) {
    int i = threadIdx.x;  // 0..255 = (m, o)
    if (i >= MM * OO) return;
    int o = i & 31;
    float mean = g_bnsum[i] * (1.f / NN);
    float var = g_bnsq[i] * (1.f / NN) - mean * mean;
    float sc = gamma[o] * rsqrtf(var + BN_EPS);
    g_scale[i] = sc;
    g_shift[i] = beta[o] - mean * sc;
}

// ---------------- 9: normalize + relu + transpose via shared tile ---------------
#define TN 32
#define SHF4 65   // padded row stride in float4 (64 data + 1 pad)
__global__ void k_output(float* __restrict__ out) {
    __shared__ __align__(16) float4 sh[TN * SHF4];
    __shared__ float ssc[MM * OO], ssh[MM * OO];
    int tid = threadIdx.x;
    int nbase = blockIdx.x * TN;
    int nmax = NN - nbase; if (nmax > TN) nmax = TN;

    ssc[tid] = g_scale[tid];
    ssh[tid] = g_shift[tid];

    const float4* src = (const float4*)&g_outpre[(size_t)nbase * FF];
    for (int i = tid; i < nmax * 64; i += 256) {
        int nl = i >> 6, j = i & 63;
        sh[nl * SHF4 + j] = src[i];
    }
    __syncthreads();

    for (int i = tid; i < MM * TN * 8; i += 256) {
        int m = i >> 8;
        int nl = (i >> 3) & 31;
        int o4 = i & 7;
        if (nl >= nmax) continue;
        float4 v = sh[nl * SHF4 + m * 8 + o4];
        int si = m * OO + o4 * 4;
        float4 r;
        r.x = fmaxf(0.f, v.x * ssc[si + 0] + ssh[si + 0]);
        r.y = fmaxf(0.f, v.y * ssc[si + 1] + ssh[si + 1]);
        r.z = fmaxf(0.f, v.z * ssc[si + 2] + ssh[si + 2]);
        r.w = fmaxf(0.f, v.w * ssc[si + 3] + ssh[si + 3]);
        ((float4*)out)[((size_t)m * NN + nbase + nl) * 8 + o4] = r;
    }
}

// ---------------- 10: cleanup -> restore zeroed state for next replay ----------
__global__ void k_cleanup() {
    int i = blockIdx.x * blockDim.x + threadIdx.x;
    if (i < NN) { g_deg[i] = 0.f; g_cnt[i] = 0; }
    if (i < MM * OO) { g_bnsum[i] = 0.f; g_bnsq[i] = 0.f; }
    if (i < SCAN_NBLK) { g_scan_flag[i] = 0; g_scan_val[i] = 0; }
}

// ------------------------------------------------------------------------------
extern "C" void kernel_launch(void* const* d_in, const int* in_sizes, int n_in,
                              void* d_out, int out_size) {
    const float* x      = (const float*)d_in[0];
    const int*   ei     = (const int*)d_in[1];
    const float* ew     = (const float*)d_in[2];
    const float* W      = (const float*)d_in[3];
    const float* bias   = (const float*)d_in[4];
    const float* gamma  = (const float*)d_in[5];
    const float* beta   = (const float*)d_in[6];
    float* out          = (float*)d_out;

    k_degcnt_xconv<<<(NN * MM * 16 + 255) / 256, 256>>>(x, ei, ew);  // 1
    k_scan_dinv<<<SCAN_NBLK, 256>>>();                               // 2
    k_fill<<<(EE + 255) / 256, 256>>>(ei, ew);                       // 3
    k_spmm_h<0><<<(NN / 2 * 32 + 255) / 256, 256>>>();               // 4 <- profiled
    k_spmm_h<1><<<(NN / 2 * 32 + 255) / 256, 256>>>();               // 5
    k_combine_mma<<<(NN * MM) / 128, 256>>>(W, bias);                // 6
    k_stats<<<(NN + 255) / 256, 256>>>();                            // 7
    k_finalize<<<1, 256>>>(gamma, beta);                             // 8
    k_output<<<(NN + TN - 1) / TN, 256>>>(out);                      // 9
    k_cleanup<<<(NN + 255) / 256, 256>>>();                          // 10
}

// round 16
// speedup vs baseline: 1.1061x; 1.0384x over previous
#include <cuda_runtime.h>
#include <cuda_fp16.h>
#include <stdint.h>

// Problem constants (fixed shapes for this problem instance)
#define NN 50000       // nodes
#define EE 800000      // edges
#define MM 8           // B*T
#define CC 32          // in channels
#define OO 32          // out channels
#define FF 256         // MM*CC features per node
#define BN_EPS 1e-5f
#define SCAN_NBLK 13   // ceil(NN / 4096)

// ---------------- scratch (device globals; no allocation allowed) -------------
// Launch order relies on these being zero at entry: first call uses CUDA static
// zero-init; k_cleanup (last launch) restores zeroed state for every replay.
__device__ float g_deg[NN];
__device__ float g_dinv[NN];
__device__ int   g_cnt[NN];          // histogram by dst, reused as fill cursor
__device__ int   g_rowptr[NN + 1];
__device__ __align__(16) uint2 g_edge[EE];              // (src, half2(w,w))
__device__ __align__(16) __half g_xh[(size_t)NN * FF];  // x, node-major fp16
__device__ __align__(16) __half g_t1h[(size_t)NN * FF]; // L x (fp16)
__device__ __align__(16) __half g_t2h[(size_t)NN * FF]; // L(Lx) raw (fp16)
__device__ __align__(16) float g_outpre[(size_t)NN * FF]; // pre-BN [r=n*8+m][32]
__device__ float g_bnsum[MM * OO];
__device__ float g_bnsq[MM * OO];
__device__ int   g_scan_val[SCAN_NBLK];
__device__ int   g_scan_flag[SCAN_NBLK];

// ---------------- mma helpers ---------------------------------------------------
__device__ __forceinline__ void ldm_x4(uint32_t& r0, uint32_t& r1,
                                       uint32_t& r2, uint32_t& r3, uint32_t a) {
    asm volatile("ldmatrix.sync.aligned.m8n8.x4.shared.b16 {%0,%1,%2,%3}, [%4];"
                 : "=r"(r0), "=r"(r1), "=r"(r2), "=r"(r3) : "r"(a));
}
__device__ __forceinline__ void mma16816(float* d, uint32_t a0, uint32_t a1,
                                         uint32_t a2, uint32_t a3,
                                         uint32_t b0, uint32_t b1) {
    asm volatile(
        "mma.sync.aligned.m16n8k16.row.col.f32.f16.f16.f32 "
        "{%0,%1,%2,%3}, {%4,%5,%6,%7}, {%8,%9}, {%0,%1,%2,%3};"
        : "+f"(d[0]), "+f"(d[1]), "+f"(d[2]), "+f"(d[3])
        : "r"(a0), "r"(a1), "r"(a2), "r"(a3), "r"(b0), "r"(b1));
}

// ---------------- 1: degree/count atomics + x->fp16 conversion (fused) ---------
__global__ void k_degcnt_xconv(const float* __restrict__ x,
                               const int* __restrict__ ei,
                               const float* __restrict__ ew) {
    int t = blockIdx.x * blockDim.x + threadIdx.x;
    if (t < EE) {
        int s = ei[t];
        int d = ei[EE + t];
        atomicAdd(&g_deg[s], ew[t]);
        atomicAdd(&g_cnt[d], 1);
    }
    if (t < NN * MM * 16) {
        int c2 = t & 15;
        int m = (t >> 4) & 7;
        int n = t >> 7;
        float2 v = *(const float2*)&x[((size_t)m * NN + n) * CC + c2 * 2];
        *(__half2*)&g_xh[(size_t)n * FF + m * CC + c2 * 2] =
            __floats2half2_rn(v.x, v.y);
    }
}

// ---------------- 2: scan(cnt)->rowptr  +  dinv (fused) ------------------------
__global__ void k_scan_dinv() {
    __shared__ int s_wsum[8];
    __shared__ int s_prev;
    int tid = threadIdx.x, b = blockIdx.x;
    int lane = tid & 31, w = tid >> 5;

    for (int i = b * 4096 + tid; i < (b + 1) * 4096 && i < NN; i += 256) {
        float dg = g_deg[i];
        g_dinv[i] = (dg > 0.f) ? rsqrtf(dg) : 0.f;
    }

    int base = b * 4096 + tid * 16;
    int v[16];
    int run = 0;
    #pragma unroll
    for (int j = 0; j < 16; j++) {
        int i = base + j;
        int c = 0;
        if (i < NN) { c = g_cnt[i]; g_cnt[i] = 0; }
        run += c;
        v[j] = run;   // inclusive within thread
    }
    int sc = run;
    #pragma unroll
    for (int off = 1; off < 32; off <<= 1) {
        int t2 = __shfl_up_sync(0xffffffffu, sc, off);
        if (lane >= off) sc += t2;
    }
    if (lane == 31) s_wsum[w] = sc;
    __syncthreads();
    if (w == 0) {
        int xv = (lane < 8) ? s_wsum[lane] : 0;
        #pragma unroll
        for (int off = 1; off < 8; off <<= 1) {
            int t2 = __shfl_up_sync(0xffffffffu, xv, off);
            if (lane >= off) xv += t2;
        }
        if (lane < 8) s_wsum[lane] = xv;
    }
    __syncthreads();
    int thread_excl = sc - run + (w ? s_wsum[w - 1] : 0);
    int block_total = s_wsum[7];
    if (tid == 0) {
        int prev = 0;
        if (b > 0) {
            while (((volatile int*)g_scan_flag)[b - 1] == 0) { }
            __threadfence();
            prev = g_scan_val[b - 1];
        }
        g_scan_val[b] = prev + block_total;
        __threadfence();
        ((volatile int*)g_scan_flag)[b] = 1;
        s_prev = prev;
    }
    __syncthreads();
    int off0 = s_prev + thread_excl;
    #pragma unroll
    for (int j = 0; j < 16; j++) {
        int i = base + j;
        if (i < NN) g_rowptr[i + 1] = off0 + v[j];
    }
    if (b == 0 && tid == 0) g_rowptr[0] = 0;
}

// ---------------- 3: CSR fill, packed (src, half2(w,w)) ------------------------
__global__ void k_fill(const int* __restrict__ ei,
                       const float* __restrict__ ew) {
    int e = blockIdx.x * blockDim.x + threadIdx.x;
    if (e >= EE) return;
    int s = ei[e];
    int d = ei[EE + e];
    float nv = -g_dinv[s] * ew[e] * g_dinv[d];
    unsigned short h = __half_as_ushort(__float2half_rn(nv));
    unsigned hw = (unsigned)h | ((unsigned)h << 16);   // half2(w, w)
    int idx = g_rowptr[d] + atomicAdd(&g_cnt[d], 1);
    g_edge[idx] = make_uint2((unsigned)s, hw);
}

// ---------------- 4/5: SpMM — pipelined edge prefetch, HFMA2 split accum -------
// One warp per dst row; lane owns 8 halves (16B). 4 gathers in flight while the
// NEXT 4-edge packet loads (edge-load latency hidden behind current gathers).
// Even/odd edges accumulate in separate half2 chains; fp32-summed at the end.
__device__ __forceinline__ void hacc(__half2* acc, uint4 v, unsigned w) {
    __half2 w2 = *(__half2*)&w;
    const __half2* h = (const __half2*)&v;
    acc[0] = __hfma2(h[0], w2, acc[0]);
    acc[1] = __hfma2(h[1], w2, acc[1]);
    acc[2] = __hfma2(h[2], w2, acc[2]);
    acc[3] = __hfma2(h[3], w2, acc[3]);
}

template <int MODE>
__global__ void __launch_bounds__(256, 6) k_spmm_h() {
    int row = (blockIdx.x * blockDim.x + threadIdx.x) >> 5;
    int lane = threadIdx.x & 31;
    if (row >= NN) return;
    int e = g_rowptr[row], end = g_rowptr[row + 1];

    const char* __restrict__ vin =
        (MODE == 0) ? (const char*)g_xh : (const char*)g_t1h;
    uint4* __restrict__ vout =
        (MODE == 0) ? (uint4*)g_t1h : (uint4*)g_t2h;

    __half2 zero = __floats2half2_rn(0.f, 0.f);
    __half2 aA[4] = {zero, zero, zero, zero};
    __half2 aB[4] = {zero, zero, zero, zero};
    unsigned lb = (unsigned)lane << 4;

    // peel to even edge index (16B-aligned packets)
    if ((e & 1) && e < end) {
        uint2 E = g_edge[e];
        uint4 V = *(const uint4*)(vin + ((E.x << 9) + lb));
        hacc(aA, V, E.y);
        e++;
    }

    if (e + 4 <= end) {
        uint4 P0 = *(const uint4*)&g_edge[e];       // edges e, e+1
        uint4 P1 = *(const uint4*)&g_edge[e + 2];   // edges e+2, e+3
        #pragma unroll 1
        while (e + 8 <= end) {
            uint4 V0 = *(const uint4*)(vin + ((P0.x << 9) + lb));
            uint4 V1 = *(const uint4*)(vin + ((P0.z << 9) + lb));
            uint4 V2 = *(const uint4*)(vin + ((P1.x << 9) + lb));
            uint4 V3 = *(const uint4*)(vin + ((P1.z << 9) + lb));
            uint4 N0 = *(const uint4*)&g_edge[e + 4];   // prefetch next packet
            uint4 N1 = *(const uint4*)&g_edge[e + 6];
            hacc(aA, V0, P0.y);
            hacc(aB, V1, P0.w);
            hacc(aA, V2, P1.y);
            hacc(aB, V3, P1.w);
            P0 = N0;
            P1 = N1;
            e += 4;
        }
        // final prefetched packet
        uint4 V0 = *(const uint4*)(vin + ((P0.x << 9) + lb));
        uint4 V1 = *(const uint4*)(vin + ((P0.z << 9) + lb));
        uint4 V2 = *(const uint4*)(vin + ((P1.x << 9) + lb));
        uint4 V3 = *(const uint4*)(vin + ((P1.z << 9) + lb));
        hacc(aA, V0, P0.y);
        hacc(aB, V1, P0.w);
        hacc(aA, V2, P1.y);
        hacc(aB, V3, P1.w);
        e += 4;
    }
    // tail: 0..3 edges
    #pragma unroll 1
    while (e < end) {
        uint2 E = g_edge[e];
        uint4 V = *(const uint4*)(vin + ((E.x << 9) + lb));
        hacc(aB, V, E.y);
        e++;
    }

    // combine split chains in fp32, round once to fp16
    uint4 o;
    #pragma unroll
    for (int i = 0; i < 4; i++) {
        float2 fa = __half22float2(aA[i]);
        float2 fb = __half22float2(aB[i]);
        ((__half2*)&o)[i] = __floats2half2_rn(fa.x + fb.x, fa.y + fb.y);
    }
    vout[(size_t)row * 32 + lane] = o;
}

// ---------------- 6: combine via tensor cores (mma.sync m16n8k16) --------------
// out[r,:] = x[r]@(W0-W2) + t1[r]@W1 + t2[r]@(2*W2) + bias,  r = n*8+m.
#define SAS 104   // smem row stride in halves (96 data + 8 pad)
__global__ void __launch_bounds__(256) k_combine_mma(const float* __restrict__ W,
                                                     const float* __restrict__ bias) {
    __shared__ __align__(16) __half sA[128 * SAS];
    __shared__ __align__(16) __half sW[32 * SAS];
    __shared__ float sB[OO];
    int tid = threadIdx.x;

    // weight prep: Wt[o][k]: k<32 -> W0-W2, k<64 -> W1, else 2*W2
    for (int i = tid; i < 32 * 96; i += 256) {
        int o = i / 96, k = i % 96;
        float v;
        if (k < 32)      v = W[k * 32 + o] - W[2048 + k * 32 + o];
        else if (k < 64) v = W[1024 + (k - 32) * 32 + o];
        else             v = 2.f * W[2048 + (k - 64) * 32 + o];
        sW[o * SAS + k] = __float2half_rn(v);
    }
    if (tid < OO) sB[tid] = bias[tid];

    // stage A rows: 128 rows x (x|t1|t2) = 128 x 96 halves
    int rbase = blockIdx.x * 128;
    const uint4* gx = (const uint4*)g_xh + (size_t)rbase * 4;
    const uint4* g1 = (const uint4*)g_t1h + (size_t)rbase * 4;
    const uint4* g2 = (const uint4*)g_t2h + (size_t)rbase * 4;
    for (int i = tid; i < 512; i += 256) {   // 128 rows x 4 16B-chunks
        int rl = i >> 2, q = i & 3;
        *(uint4*)&sA[rl * SAS + q * 8]      = gx[i];
        *(uint4*)&sA[rl * SAS + 32 + q * 8] = g1[i];
        *(uint4*)&sA[rl * SAS + 64 + q * 8] = g2[i];
    }
    __syncthreads();

    int w = tid >> 5, l = tid & 31;
    int colb = (l & 3) * 2;

    float d[4][4];
    #pragma unroll
    for (int t = 0; t < 4; t++) {
        float b0 = sB[t * 8 + colb], b1 = sB[t * 8 + colb + 1];
        d[t][0] = b0; d[t][1] = b1; d[t][2] = b0; d[t][3] = b1;
    }

    int rowi = l & 7;
    int quad = l >> 3;
    int r_loc = w * 16 + rowi + (quad & 1) * 8;
    int cq = (quad >> 1) * 8;
    uint32_t abase = (uint32_t)__cvta_generic_to_shared(&sA[r_loc * SAS + cq]);

    #pragma unroll
    for (int ks = 0; ks < 6; ks++) {
        int c0 = ks * 16;
        uint32_t a0, a1, a2, a3;
        ldm_x4(a0, a1, a2, a3, abase + c0 * 2);
        #pragma unroll
        for (int t = 0; t < 4; t++) {
            int n = t * 8 + (l >> 2);
            uint32_t b0 = *(const uint32_t*)&sW[n * SAS + c0 + colb];
            uint32_t b1 = *(const uint32_t*)&sW[n * SAS + c0 + 8 + colb];
            mma16816(d[t], a0, a1, a2, a3, b0, b1);
        }
    }

    // store D: rows r0 (l>>2) and r0+8; cols t*8 + colb (+1)
    int r0 = rbase + w * 16 + (l >> 2);
    #pragma unroll
    for (int t = 0; t < 4; t++) {
        int c = t * 8 + colb;
        *(float2*)&g_outpre[(size_t)r0 * 32 + c] = make_float2(d[t][0], d[t][1]);
        *(float2*)&g_outpre[(size_t)(r0 + 8) * 32 + c] = make_float2(d[t][2], d[t][3]);
    }
}

// ---------------- 7: BN statistics (streaming, coalesced) ----------------------
__global__ void k_stats() {
    int tid = threadIdx.x;
    int nbase = blockIdx.x * 256;
    int rows = NN - nbase; if (rows > 256) rows = 256;
    float s0 = 0.f, sq0 = 0.f, s1 = 0.f, sq1 = 0.f;
    const float* p = &g_outpre[(size_t)nbase * FF + tid];
    int r = 0;
    #pragma unroll 4
    for (; r + 2 <= rows; r += 2) {
        float v0 = p[(size_t)r * FF];
        float v1 = p[(size_t)(r + 1) * FF];
        s0 += v0; sq0 += v0 * v0;
        s1 += v1; sq1 += v1 * v1;
    }
    if (r < rows) {
        float v0 = p[(size_t)r * FF];
        s0 += v0; sq0 += v0 * v0;
    }
    atomicAdd(&g_bnsum[tid], s0 + s1);
    atomicAdd(&g_bnsq[tid], sq0 + sq1);
}

// ---------------- 8: normalize + relu + transpose (finalize fused) -------------
// Each block computes the 256 scale/shift values from bnsum/bnsq directly.
#define TN 32
#define SHF4 65   // padded row stride in float4 (64 data + 1 pad)
__global__ void k_output(const float* __restrict__ gamma,
                         const float* __restrict__ beta,
                         float* __restrict__ out) {
    __shared__ __align__(16) float4 sh[TN * SHF4];
    __shared__ float ssc[MM * OO], ssh[MM * OO];
    int tid = threadIdx.x;
    int nbase = blockIdx.x * TN;
    int nmax = NN - nbase; if (nmax > TN) nmax = TN;

    {   // fused finalize: tid = (m, o)
        int o = tid & 31;
        float mean = g_bnsum[tid] * (1.f / NN);
        float var = g_bnsq[tid] * (1.f / NN) - mean * mean;
        float sc = gamma[o] * rsqrtf(var + BN_EPS);
        ssc[tid] = sc;
        ssh[tid] = beta[o] - mean * sc;
    }

    const float4* src = (const float4*)&g_outpre[(size_t)nbase * FF];
    for (int i = tid; i < nmax * 64; i += 256) {
        int nl = i >> 6, j = i & 63;
        sh[nl * SHF4 + j] = src[i];
    }
    __syncthreads();

    for (int i = tid; i < MM * TN * 8; i += 256) {
        int m = i >> 8;
        int nl = (i >> 3) & 31;
        int o4 = i & 7;
        if (nl >= nmax) continue;
        float4 v = sh[nl * SHF4 + m * 8 + o4];
        int si = m * OO + o4 * 4;
        float4 r;
        r.x = fmaxf(0.f, v.x * ssc[si + 0] + ssh[si + 0]);
        r.y = fmaxf(0.f, v.y * ssc[si + 1] + ssh[si + 1]);
        r.z = fmaxf(0.f, v.z * ssc[si + 2] + ssh[si + 2]);
        r.w = fmaxf(0.f, v.w * ssc[si + 3] + ssh[si + 3]);
        ((float4*)out)[((size_t)m * NN + nbase + nl) * 8 + o4] = r;
    }
}

// ---------------- 9: cleanup -> restore zeroed state for next replay -----------
__global__ void k_cleanup() {
    int i = blockIdx.x * blockDim.x + threadIdx.x;
    if (i < NN) { g_deg[i] = 0.f; g_cnt[i] = 0; }
    if (i < MM * OO) { g_bnsum[i] = 0.f; g_bnsq[i] = 0.f; }
    if (i < SCAN_NBLK) { g_scan_flag[i] = 0; g_scan_val[i] = 0; }
}

// ------------------------------------------------------------------------------
extern "C" void kernel_launch(void* const* d_in, const int* in_sizes, int n_in,
                              void* d_out, int out_size) {
    const float* x      = (const float*)d_in[0];
    const int*   ei     = (const int*)d_in[1];
    const float* ew     = (const float*)d_in[2];
    const float* W      = (const float*)d_in[3];
    const float* bias   = (const float*)d_in[4];
    const float* gamma  = (const float*)d_in[5];
    const float* beta   = (const float*)d_in[6];
    float* out          = (float*)d_out;

    k_degcnt_xconv<<<(NN * MM * 16 + 255) / 256, 256>>>(x, ei, ew);  // 1
    k_scan_dinv<<<SCAN_NBLK, 256>>>();                               // 2
    k_fill<<<(EE + 255) / 256, 256>>>(ei, ew);                       // 3
    k_spmm_h<0><<<(NN * 32 + 255) / 256, 256>>>();                   // 4 <- profiled
    k_spmm_h<1><<<(NN * 32 + 255) / 256, 256>>>();                   // 5
    k_combine_mma<<<(NN * MM) / 128, 256>>>(W, bias);                // 6
    k_stats<<<(NN + 255) / 256, 256>>>();                            // 7
    k_output<<<(NN + TN - 1) / TN, 256>>>(gamma, beta, out);         // 8
    k_cleanup<<<(NN + 255) / 256, 256>>>();                          // 9
}

// round 17
// speedup vs baseline: 1.1702x; 1.0579x over previous
#include <cuda_runtime.h>
#include <cuda_fp16.h>
#include <stdint.h>

// Problem constants (fixed shapes for this problem instance)
#define NN 50000       // nodes
#define EE 800000      // edges
#define MM 8           // B*T
#define CC 32          // in channels
#define OO 32          // out channels
#define FF 256         // MM*CC features per node
#define BN_EPS 1e-5f
#define SCAN_NBLK 13   // ceil(NN / 4096)

// ---------------- scratch (device globals; no allocation allowed) -------------
// State contract: every buffer is zero at first use on every replay.
// First call: CUDA static zero-init. Subsequent replays: each buffer is
// re-zeroed by a LATER kernel in the same replay, after its last read:
//   g_cnt       zeroed in k_scan_dinv (during scan) -> rebuilt as cursor in
//               k_fill -> zeroed again in k_spmm_h<0>
//   g_deg, g_scan_flag, g_scan_val   zeroed in k_fill (after last read)
//   g_bnsum, g_bnsq  zeroed in k_degcnt_xconv (before same-replay accumulation)
__device__ float g_deg[NN];
__device__ float g_dinv[NN];
__device__ int   g_cnt[NN];
__device__ int   g_rowptr[NN + 1];
__device__ __align__(16) uint2 g_edge[EE];              // (src, half2(w,w))
__device__ __align__(16) __half g_xh[(size_t)NN * FF];  // x, node-major fp16
__device__ __align__(16) __half g_t1h[(size_t)NN * FF]; // L x (fp16)
__device__ __align__(16) __half g_t2h[(size_t)NN * FF]; // L(Lx) raw (fp16)
__device__ __align__(16) __half g_outh[(size_t)NN * FF];// pre-BN fp16 [r=n*8+m][32]
__device__ float g_bnsum[MM * OO];
__device__ float g_bnsq[MM * OO];
__device__ int   g_scan_val[SCAN_NBLK];
__device__ int   g_scan_flag[SCAN_NBLK];

// ---------------- mma helpers ---------------------------------------------------
__device__ __forceinline__ void ldm_x4(uint32_t& r0, uint32_t& r1,
                                       uint32_t& r2, uint32_t& r3, uint32_t a) {
    asm volatile("ldmatrix.sync.aligned.m8n8.x4.shared.b16 {%0,%1,%2,%3}, [%4];"
                 : "=r"(r0), "=r"(r1), "=r"(r2), "=r"(r3) : "r"(a));
}
__device__ __forceinline__ void mma16816(float* d, uint32_t a0, uint32_t a1,
                                         uint32_t a2, uint32_t a3,
                                         uint32_t b0, uint32_t b1) {
    asm volatile(
        "mma.sync.aligned.m16n8k16.row.col.f32.f16.f16.f32 "
        "{%0,%1,%2,%3}, {%4,%5,%6,%7}, {%8,%9}, {%0,%1,%2,%3};"
        : "+f"(d[0]), "+f"(d[1]), "+f"(d[2]), "+f"(d[3])
        : "r"(a0), "r"(a1), "r"(a2), "r"(a3), "r"(b0), "r"(b1));
}

// ---------------- 1: degree/count atomics + x->fp16 + BN-sum reset -------------
__global__ void k_degcnt_xconv(const float* __restrict__ x,
                               const int* __restrict__ ei,
                               const float* __restrict__ ew) {
    int t = blockIdx.x * blockDim.x + threadIdx.x;
    if (t < MM * OO) { g_bnsum[t] = 0.f; g_bnsq[t] = 0.f; }  // reset for this replay
    if (t < EE) {
        int s = ei[t];
        int d = ei[EE + t];
        atomicAdd(&g_deg[s], ew[t]);
        atomicAdd(&g_cnt[d], 1);
    }
    if (t < NN * MM * 16) {
        int c2 = t & 15;
        int m = (t >> 4) & 7;
        int n = t >> 7;
        float2 v = *(const float2*)&x[((size_t)m * NN + n) * CC + c2 * 2];
        *(__half2*)&g_xh[(size_t)n * FF + m * CC + c2 * 2] =
            __floats2half2_rn(v.x, v.y);
    }
}

// ---------------- 2: scan(cnt)->rowptr  +  dinv (fused) ------------------------
__global__ void k_scan_dinv() {
    __shared__ int s_wsum[8];
    __shared__ int s_prev;
    int tid = threadIdx.x, b = blockIdx.x;
    int lane = tid & 31, w = tid >> 5;

    for (int i = b * 4096 + tid; i < (b + 1) * 4096 && i < NN; i += 256) {
        float dg = g_deg[i];
        g_dinv[i] = (dg > 0.f) ? rsqrtf(dg) : 0.f;
    }

    int base = b * 4096 + tid * 16;
    int v[16];
    int run = 0;
    #pragma unroll
    for (int j = 0; j < 16; j++) {
        int i = base + j;
        int c = 0;
        if (i < NN) { c = g_cnt[i]; g_cnt[i] = 0; }
        run += c;
        v[j] = run;   // inclusive within thread
    }
    int sc = run;
    #pragma unroll
    for (int off = 1; off < 32; off <<= 1) {
        int t2 = __shfl_up_sync(0xffffffffu, sc, off);
        if (lane >= off) sc += t2;
    }
    if (lane == 31) s_wsum[w] = sc;
    __syncthreads();
    if (w == 0) {
        int xv = (lane < 8) ? s_wsum[lane] : 0;
        #pragma unroll
        for (int off = 1; off < 8; off <<= 1) {
            int t2 = __shfl_up_sync(0xffffffffu, xv, off);
            if (lane >= off) xv += t2;
        }
        if (lane < 8) s_wsum[lane] = xv;
    }
    __syncthreads();
    int thread_excl = sc - run + (w ? s_wsum[w - 1] : 0);
    int block_total = s_wsum[7];
    if (tid == 0) {
        int prev = 0;
        if (b > 0) {
            while (((volatile int*)g_scan_flag)[b - 1] == 0) { }
            __threadfence();
            prev = g_scan_val[b - 1];
        }
        g_scan_val[b] = prev + block_total;
        __threadfence();
        ((volatile int*)g_scan_flag)[b] = 1;
        s_prev = prev;
    }
    __syncthreads();
    int off0 = s_prev + thread_excl;
    #pragma unroll
    for (int j = 0; j < 16; j++) {
        int i = base + j;
        if (i < NN) g_rowptr[i + 1] = off0 + v[j];
    }
    if (b == 0 && tid == 0) g_rowptr[0] = 0;
}

// ---------------- 3: CSR fill + deg/scan-state reset ---------------------------
__global__ void k_fill(const int* __restrict__ ei,
                       const float* __restrict__ ew) {
    int e = blockIdx.x * blockDim.x + threadIdx.x;
    if (e >= EE) return;
    if (e < NN) g_deg[e] = 0.f;                       // reset for next replay
    if (e < SCAN_NBLK) { g_scan_flag[e] = 0; g_scan_val[e] = 0; }
    int s = ei[e];
    int d = ei[EE + e];
    float nv = -g_dinv[s] * ew[e] * g_dinv[d];
    unsigned short h = __half_as_ushort(__float2half_rn(nv));
    unsigned hw = (unsigned)h | ((unsigned)h << 16);   // half2(w, w)
    int idx = g_rowptr[d] + atomicAdd(&g_cnt[d], 1);
    g_edge[idx] = make_uint2((unsigned)s, hw);
}

// ---------------- 4/5: SpMM — pipelined edge prefetch, HFMA2 split accum -------
// One warp per dst row; lane owns 8 halves (16B). 4 gathers in flight while the
// NEXT 4-edge packet loads. Even/odd edges in separate half2 chains; fp32 sum.
// MODE 0 also zeroes g_cnt (cursor state) for the next replay.
__device__ __forceinline__ void hacc(__half2* acc, uint4 v, unsigned w) {
    __half2 w2 = *(__half2*)&w;
    const __half2* h = (const __half2*)&v;
    acc[0] = __hfma2(h[0], w2, acc[0]);
    acc[1] = __hfma2(h[1], w2, acc[1]);
    acc[2] = __hfma2(h[2], w2, acc[2]);
    acc[3] = __hfma2(h[3], w2, acc[3]);
}

template <int MODE>
__global__ void __launch_bounds__(256, 6) k_spmm_h() {
    int gid = blockIdx.x * blockDim.x + threadIdx.x;
    if (MODE == 0 && gid < NN) g_cnt[gid] = 0;        // reset fill cursor
    int row = gid >> 5;
    int lane = threadIdx.x & 31;
    if (row >= NN) return;
    int e = g_rowptr[row], end = g_rowptr[row + 1];

    const char* __restrict__ vin =
        (MODE == 0) ? (const char*)g_xh : (const char*)g_t1h;
    uint4* __restrict__ vout =
        (MODE == 0) ? (uint4*)g_t1h : (uint4*)g_t2h;

    __half2 zero = __floats2half2_rn(0.f, 0.f);
    __half2 aA[4] = {zero, zero, zero, zero};
    __half2 aB[4] = {zero, zero, zero, zero};
    unsigned lb = (unsigned)lane << 4;

    // peel to even edge index (16B-aligned packets)
    if ((e & 1) && e < end) {
        uint2 E = g_edge[e];
        uint4 V = *(const uint4*)(vin + ((E.x << 9) + lb));
        hacc(aA, V, E.y);
        e++;
    }

    if (e + 4 <= end) {
        uint4 P0 = *(const uint4*)&g_edge[e];       // edges e, e+1
        uint4 P1 = *(const uint4*)&g_edge[e + 2];   // edges e+2, e+3
        #pragma unroll 1
        while (e + 8 <= end) {
            uint4 V0 = *(const uint4*)(vin + ((P0.x << 9) + lb));
            uint4 V1 = *(const uint4*)(vin + ((P0.z << 9) + lb));
            uint4 V2 = *(const uint4*)(vin + ((P1.x << 9) + lb));
            uint4 V3 = *(const uint4*)(vin + ((P1.z << 9) + lb));
            uint4 N0 = *(const uint4*)&g_edge[e + 4];   // prefetch next packet
            uint4 N1 = *(const uint4*)&g_edge[e + 6];
            hacc(aA, V0, P0.y);
            hacc(aB, V1, P0.w);
            hacc(aA, V2, P1.y);
            hacc(aB, V3, P1.w);
            P0 = N0;
            P1 = N1;
            e += 4;
        }
        // final prefetched packet
        uint4 V0 = *(const uint4*)(vin + ((P0.x << 9) + lb));
        uint4 V1 = *(const uint4*)(vin + ((P0.z << 9) + lb));
        uint4 V2 = *(const uint4*)(vin + ((P1.x << 9) + lb));
        uint4 V3 = *(const uint4*)(vin + ((P1.z << 9) + lb));
        hacc(aA, V0, P0.y);
        hacc(aB, V1, P0.w);
        hacc(aA, V2, P1.y);
        hacc(aB, V3, P1.w);
        e += 4;
    }
    // tail: 0..3 edges
    #pragma unroll 1
    while (e < end) {
        uint2 E = g_edge[e];
        uint4 V = *(const uint4*)(vin + ((E.x << 9) + lb));
        hacc(aB, V, E.y);
        e++;
    }

    // combine split chains in fp32, round once to fp16
    uint4 o;
    #pragma unroll
    for (int i = 0; i < 4; i++) {
        float2 fa = __half22float2(aA[i]);
        float2 fb = __half22float2(aB[i]);
        ((__half2*)&o)[i] = __floats2half2_rn(fa.x + fb.x, fa.y + fb.y);
    }
    vout[(size_t)row * 32 + lane] = o;
}

// ---------------- 6: combine via tensor cores (mma.sync m16n8k16) --------------
// out[r,:] = x[r]@(W0-W2) + t1[r]@W1 + t2[r]@(2*W2) + bias,  r = n*8+m.
// Result stored fp16 to g_outh.
#define SAS 104   // smem row stride in halves (96 data + 8 pad)
__global__ void __launch_bounds__(256) k_combine_mma(const float* __restrict__ W,
                                                     const float* __restrict__ bias) {
    __shared__ __align__(16) __half sA[128 * SAS];
    __shared__ __align__(16) __half sW[32 * SAS];
    __shared__ float sB[OO];
    int tid = threadIdx.x;

    // weight prep: Wt[o][k]: k<32 -> W0-W2, k<64 -> W1, else 2*W2
    for (int i = tid; i < 32 * 96; i += 256) {
        int o = i / 96, k = i % 96;
        float v;
        if (k < 32)      v = W[k * 32 + o] - W[2048 + k * 32 + o];
        else if (k < 64) v = W[1024 + (k - 32) * 32 + o];
        else             v = 2.f * W[2048 + (k - 64) * 32 + o];
        sW[o * SAS + k] = __float2half_rn(v);
    }
    if (tid < OO) sB[tid] = bias[tid];

    // stage A rows: 128 rows x (x|t1|t2) = 128 x 96 halves
    int rbase = blockIdx.x * 128;
    const uint4* gx = (const uint4*)g_xh + (size_t)rbase * 4;
    const uint4* g1 = (const uint4*)g_t1h + (size_t)rbase * 4;
    const uint4* g2 = (const uint4*)g_t2h + (size_t)rbase * 4;
    for (int i = tid; i < 512; i += 256) {   // 128 rows x 4 16B-chunks
        int rl = i >> 2, q = i & 3;
        *(uint4*)&sA[rl * SAS + q * 8]      = gx[i];
        *(uint4*)&sA[rl * SAS + 32 + q * 8] = g1[i];
        *(uint4*)&sA[rl * SAS + 64 + q * 8] = g2[i];
    }
    __syncthreads();

    int w = tid >> 5, l = tid & 31;
    int colb = (l & 3) * 2;

    float d[4][4];
    #pragma unroll
    for (int t = 0; t < 4; t++) {
        float b0 = sB[t * 8 + colb], b1 = sB[t * 8 + colb + 1];
        d[t][0] = b0; d[t][1] = b1; d[t][2] = b0; d[t][3] = b1;
    }

    int rowi = l & 7;
    int quad = l >> 3;
    int r_loc = w * 16 + rowi + (quad & 1) * 8;
    int cq = (quad >> 1) * 8;
    uint32_t abase = (uint32_t)__cvta_generic_to_shared(&sA[r_loc * SAS + cq]);

    #pragma unroll
    for (int ks = 0; ks < 6; ks++) {
        int c0 = ks * 16;
        uint32_t a0, a1, a2, a3;
        ldm_x4(a0, a1, a2, a3, abase + c0 * 2);
        #pragma unroll
        for (int t = 0; t < 4; t++) {
            int n = t * 8 + (l >> 2);
            uint32_t b0 = *(const uint32_t*)&sW[n * SAS + c0 + colb];
            uint32_t b1 = *(const uint32_t*)&sW[n * SAS + c0 + 8 + colb];
            mma16816(d[t], a0, a1, a2, a3, b0, b1);
        }
    }

    // store D as fp16: rows r0 (l>>2) and r0+8; cols t*8 + colb (+1)
    int r0 = rbase + w * 16 + (l >> 2);
    #pragma unroll
    for (int t = 0; t < 4; t++) {
        int c = t * 8 + colb;
        *(__half2*)&g_outh[(size_t)r0 * 32 + c] =
            __floats2half2_rn(d[t][0], d[t][1]);
        *(__half2*)&g_outh[(size_t)(r0 + 8) * 32 + c] =
            __floats2half2_rn(d[t][2], d[t][3]);
    }
}

// ---------------- 7: BN statistics (streaming fp16, coalesced) -----------------
__global__ void k_stats() {
    int tid = threadIdx.x;
    int nbase = blockIdx.x * 256;
    int rows = NN - nbase; if (rows > 256) rows = 256;
    float s0 = 0.f, sq0 = 0.f, s1 = 0.f, sq1 = 0.f;
    const __half* p = &g_outh[(size_t)nbase * FF + tid];
    int r = 0;
    #pragma unroll 4
    for (; r + 2 <= rows; r += 2) {
        float v0 = __half2float(p[(size_t)r * FF]);
        float v1 = __half2float(p[(size_t)(r + 1) * FF]);
        s0 += v0; sq0 += v0 * v0;
        s1 += v1; sq1 += v1 * v1;
    }
    if (r < rows) {
        float v0 = __half2float(p[(size_t)r * FF]);
        s0 += v0; sq0 += v0 * v0;
    }
    atomicAdd(&g_bnsum[tid], s0 + s1);
    atomicAdd(&g_bnsq[tid], sq0 + sq1);
}

// ---------------- 8: normalize + relu + transpose (finalize fused) -------------
#define TN 32
#define SHF4 65   // padded row stride in float4 (64 data + 1 pad)
__global__ void k_output(const float* __restrict__ gamma,
                         const float* __restrict__ beta,
                         float* __restrict__ out) {
    __shared__ __align__(16) float4 sh[TN * SHF4];
    __shared__ float ssc[MM * OO], ssh[MM * OO];
    int tid = threadIdx.x;
    int nbase = blockIdx.x * TN;
    int nmax = NN - nbase; if (nmax > TN) nmax = TN;

    {   // fused finalize: tid = (m, o)
        int o = tid & 31;
        float mean = g_bnsum[tid] * (1.f / NN);
        float var = g_bnsq[tid] * (1.f / NN) - mean * mean;
        float sc = gamma[o] * rsqrtf(var + BN_EPS);
        ssc[tid] = sc;
        ssh[tid] = beta[o] - mean * sc;
    }

    // load fp16 tile -> fp32 shared (8B/thread loads, coalesced)
    const uint2* src = (const uint2*)&g_outh[(size_t)nbase * FF];
    for (int i = tid; i < nmax * 64; i += 256) {
        uint2 u = src[i];
        float2 f0 = __half22float2(*(__half2*)&u.x);
        float2 f1 = __half22float2(*(__half2*)&u.y);
        sh[(i >> 6) * SHF4 + (i & 63)] = make_float4(f0.x, f0.y, f1.x, f1.y);
    }
    __syncthreads();

    for (int i = tid; i < MM * TN * 8; i += 256) {
        int m = i >> 8;
        int nl = (i >> 3) & 31;
        int o4 = i & 7;
        if (nl >= nmax) continue;
        float4 v = sh[nl * SHF4 + m * 8 + o4];
        int si = m * OO + o4 * 4;
        float4 r;
        r.x = fmaxf(0.f, v.x * ssc[si + 0] + ssh[si + 0]);
        r.y = fmaxf(0.f, v.y * ssc[si + 1] + ssh[si + 1]);
        r.z = fmaxf(0.f, v.z * ssc[si + 2] + ssh[si + 2]);
        r.w = fmaxf(0.f, v.w * ssc[si + 3] + ssh[si + 3]);
        ((float4*)out)[((size_t)m * NN + nbase + nl) * 8 + o4] = r;
    }
}

// ------------------------------------------------------------------------------
extern "C" void kernel_launch(void* const* d_in, const int* in_sizes, int n_in,
                              void* d_out, int out_size) {
    const float* x      = (const float*)d_in[0];
    const int*   ei     = (const int*)d_in[1];
    const float* ew     = (const float*)d_in[2];
    const float* W      = (const float*)d_in[3];
    const float* bias   = (const float*)d_in[4];
    const float* gamma  = (const float*)d_in[5];
    const float* beta   = (const float*)d_in[6];
    float* out          = (float*)d_out;

    k_degcnt_xconv<<<(NN * MM * 16 + 255) / 256, 256>>>(x, ei, ew);  // 1
    k_scan_dinv<<<SCAN_NBLK, 256>>>();                               // 2
    k_fill<<<(EE + 255) / 256, 256>>>(ei, ew);                       // 3
    k_spmm_h<0><<<(NN * 32 + 255) / 256, 256>>>();                   // 4 <- profiled
    k_spmm_h<1><<<(NN * 32 + 255) / 256, 256>>>();                   // 5
    k_combine_mma<<<(NN * MM) / 128, 256>>>(W, bias);                // 6
    k_stats<<<(NN + 255) / 256, 256>>>();                            // 7
    k_output<<<(NN + TN - 1) / TN, 256>>>(gamma, beta, out);         // 8
}